// round 7
// baseline (speedup 1.0000x reference)
#include <cuda_runtime.h>
#include <math.h>

#define N_PIX_MAX 4194304
#define N_BINS    350000
#define TAPS      901
#define HALF      450
#define CONV_THREADS 256
#define RPT       4                         // float2 output-pairs per thread
#define RING      8                         // u64 ring slots (elements mod 8)
#define HTILE     (CONV_THREADS * RPT)      // 1024 (per half)
#define TILE_OUT  (2 * HTILE)               // 2048 outputs per block
#define RAW2      (HTILE + 2*HALF + 8)      // 1932 float2 window (+refill slack)
#define PAD2      (RAW2 + (RAW2 >> 3))      // bank-conflict padding (1 per 8)
#define WSH_N     916                       // taps padded past 901 (zeros) + prefetch slack
#define P2(i)     ((i) + ((i) >> 3))

typedef unsigned long long u64;

// ---------------- device scratch (no allocations allowed) ----------------
__device__ float g_rot[TAPS];
__device__ float g_gauss[TAPS];
__device__ int   g_lo8[2];
__device__ int   g_nt8[2];
__device__ __align__(16) float g_mid[N_PIX_MAX];    // after rotational conv
__device__ __align__(16) float g_conv[N_PIX_MAX];   // after gaussian conv
__device__ float g_sums[N_BINS];
__device__ float g_cnts[N_BINS];

// ---------------- zero the bin accumulators (graph replays!) -------------
__global__ void zero_kernel() {
    int i = blockIdx.x * blockDim.x + threadIdx.x;
    int stride = gridDim.x * blockDim.x;
    for (int j = i; j < N_BINS; j += stride) {
        g_sums[j] = 0.0f;
        g_cnts[j] = 0.0f;
    }
}

// ---------------- build both kernels + support bounds on device ----------
__global__ void setup_kernel(const float* __restrict__ ln_sigma,
                             const float* __restrict__ ln_vsini) {
    __shared__ float red[1024];
    __shared__ int s_lo0, s_hi0, s_lo1, s_hi1;
    int tid = threadIdx.x;
    if (tid == 0) { s_lo0 = TAPS; s_hi0 = -1; s_lo1 = TAPS; s_hi1 = -1; }
    __syncthreads();

    float vsini = 0.9f + expf(ln_vsini[0]);
    float sigma = 0.01f + expf(ln_sigma[0]);

    float w  = 0.0f;   // rotational tap (pre-normalization)
    float gw = 0.0f;   // gaussian tap
    if (tid < TAPS) {
        float g = -4.5f + 0.01f * (float)tid;   // linspace(-4.5,4.5,901)
        float x  = (299792.458f * g / 10500.0f) / vsini;
        float x2 = fminf(x * x, 1.0f);
        if (x2 < 0.99999999f) {
            w = 2.0f * sqrtf(1.0f - x2);
            atomicMin(&s_lo0, tid);
            atomicMax(&s_hi0, tid);
        }
        float e = expf(-0.5f * g * g / (sigma * sigma));
        if (e >= 1e-12f) {                       // relative-to-peak cutoff
            atomicMin(&s_lo1, tid);
            atomicMax(&s_hi1, tid);
        }
        gw = (0.01f / (sigma * sqrtf(2.0f * 3.1415926654f))) * e;
    }

    // block sum of rotational kernel for normalization
    red[tid] = w;
    __syncthreads();
    for (int s = 512; s > 0; s >>= 1) {
        if (tid < s) red[tid] += red[tid + s];
        __syncthreads();
    }
    float total = red[0];

    if (tid < TAPS) {
        g_rot[tid]   = w / total;
        g_gauss[tid] = gw;
    }
    if (tid == 0) {
        // align support to multiples of 8 so the conv register ring is static
        int lo0 = s_lo0 & ~7;
        int lo1 = s_lo1 & ~7;
        g_lo8[0] = lo0;  g_nt8[0] = ((s_hi0 - lo0 + 1) + 7) & ~7;
        g_lo8[1] = lo1;  g_nt8[1] = ((s_hi1 - lo1 + 1) + 7) & ~7;
    }
}

// ---------------- tiled conv, packed f32x2, 8-slot ring / 4 accs ---------
// Each block produces TILE_OUT=2048 outputs: thread handles 4 pairs
// (o, o+1024). Shared input interleaved float2(in[g], in[g+1024]).
// Ring of 8 elements with only 4 consumers per tap -> refilled element is
// first read 4-5 taps (30+ issues) after its LDS: latency structurally hidden.
__global__ void __launch_bounds__(CONV_THREADS)
conv_kernel(const float* __restrict__ ext_in, int n, int which) {
    __shared__ float2 sh2[PAD2];
    __shared__ float  wsh[WSH_N];

    const float* __restrict__ in  = which ? (const float*)g_mid : ext_in;
    float* __restrict__       out = which ? g_conv : g_mid;
    const float* __restrict__ w   = which ? g_gauss : g_rot;
    const int lo8 = g_lo8[which];      // multiple of 8
    const int nt8 = g_nt8[which];      // multiple of 8

    const int tile0 = blockIdx.x * TILE_OUT;
    const int tid   = threadIdx.x;

    for (int j = tid; j < WSH_N; j += CONV_THREADS)
        wsh[j] = (j < TAPS) ? w[j] : 0.0f;
    for (int j = tid; j < RAW2; j += CONV_THREADS) {
        int g1 = tile0 - HALF + j;
        int g2 = g1 + HTILE;
        float a = (g1 >= 0 && g1 < n) ? in[g1] : 0.0f;
        float b = (g2 >= 0 && g2 < n) ? in[g2] : 0.0f;
        sh2[P2(j)] = make_float2(a, b);
    }
    __syncthreads();

    const int base = tid * RPT;        // float2-index of first output pair
    u64 x[RING];                       // ring: slot s holds element with (e-base-lo8)%8==s
    u64 acc[RPT];
#pragma unroll
    for (int s = 0; s < RING; ++s)
        x[s] = *(const u64*)&sh2[P2(base + lo8 + s)];
#pragma unroll
    for (int r = 0; r < RPT; ++r)
        acc[r] = 0ull;                 // (0.0f, 0.0f)

    int t = lo8;
    float wv_cur = wsh[t];             // prefetched scalar weight
    for (int it = 0; it < nt8; it += 8, t += 8) {
#pragma unroll
        for (int u = 0; u < 8; ++u) {  // tap tau = t + u, phase u
            float wv_nxt = wsh[t + u + 1];           // prefetch next tap's weight
            u64 wp;                                   // pack {w,w} in-register
            asm("mov.b64 %0, {%1, %1};" : "=l"(wp) : "f"(wv_cur));
            // r=0 is the last consumer of slot u (element base+tau)
            asm("fma.rn.f32x2 %0, %1, %2, %0;"
                : "+l"(acc[0]) : "l"(x[u]), "l"(wp));
            // refill slot u with element base+tau+8; first read at tap tau+5
            u64 xfill = *(const u64*)&sh2[P2(base + t + u + 8)];
            asm("fma.rn.f32x2 %0, %1, %2, %0;"
                : "+l"(acc[1]) : "l"(x[(u + 1) & 7]), "l"(wp));
            asm("fma.rn.f32x2 %0, %1, %2, %0;"
                : "+l"(acc[2]) : "l"(x[(u + 2) & 7]), "l"(wp));
            asm("fma.rn.f32x2 %0, %1, %2, %0;"
                : "+l"(acc[3]) : "l"(x[(u + 3) & 7]), "l"(wp));
            x[u] = xfill;
            wv_cur = wv_nxt;
        }
    }

    // unpack: low 32 bits = first-half output, high = second-half
    float lo_v[RPT], hi_v[RPT];
#pragma unroll
    for (int r = 0; r < RPT; ++r) {
        lo_v[r] = __int_as_float((int)(acc[r] & 0xFFFFFFFFull));
        hi_v[r] = __int_as_float((int)(acc[r] >> 32));
    }

    int o1 = tile0 + base;
    int o2 = o1 + HTILE;
    if (o1 + RPT <= n) {
        *(float4*)(out + o1) = make_float4(lo_v[0], lo_v[1], lo_v[2], lo_v[3]);
    } else {
#pragma unroll
        for (int r = 0; r < RPT; ++r)
            if (o1 + r < n) out[o1 + r] = lo_v[r];
    }
    if (o2 + RPT <= n) {
        *(float4*)(out + o2) = make_float4(hi_v[0], hi_v[1], hi_v[2], hi_v[3]);
    } else {
#pragma unroll
        for (int r = 0; r < RPT; ++r)
            if (o2 + r < n) out[o2 + r] = hi_v[r];
    }
}

// ---------------- sorted segment sum/count (run-length + atomics) --------
__global__ void seg_kernel(const int* __restrict__ ids, int n) {
    long long tidg = (long long)(blockIdx.x * blockDim.x + threadIdx.x);
    int base = (int)(tidg * 8);
    if (base >= n) return;
    int end = base + 8;
    if (end > n) end = n;

    int   cur = ids[base];
    float s = 0.0f, c = 0.0f;
    for (int k = base; k < end; ++k) {
        int id = ids[k];
        if (id != cur) {
            atomicAdd(&g_sums[cur], s);
            atomicAdd(&g_cnts[cur], c);
            cur = id; s = 0.0f; c = 0.0f;
        }
        s += g_conv[k];
        c += 1.0f;
    }
    atomicAdd(&g_sums[cur], s);
    atomicAdd(&g_cnts[cur], c);
}

// ---------------- means, clip, drop first/last bin -----------------------
__global__ void final_kernel(float* __restrict__ out, int n_out) {
    int i = blockIdx.x * blockDim.x + threadIdx.x;
    if (i < n_out) {
        int id = i + 1;
        float c = g_cnts[id];
        float m = g_sums[id] / fmaxf(c, 1.0f);
        out[i] = fminf(fmaxf(m, 0.0f), 1.0f);
    }
}

extern "C" void kernel_launch(void* const* d_in, const int* in_sizes, int n_in,
                              void* d_out, int out_size) {
    const float* flux     = (const float*)d_in[0];
    const float* ln_sigma = (const float*)d_in[1];
    const float* ln_vsini = (const float*)d_in[2];
    const int*   ids      = (const int*)d_in[3];
    int n = in_sizes[0];

    zero_kernel<<<684, 512>>>();
    setup_kernel<<<1, 1024>>>(ln_sigma, ln_vsini);

    int conv_blocks = (n + TILE_OUT - 1) / TILE_OUT;
    conv_kernel<<<conv_blocks, CONV_THREADS>>>(flux, n, 0);
    conv_kernel<<<conv_blocks, CONV_THREADS>>>(flux, n, 1);

    int seg_threads = (n + 7) / 8;
    seg_kernel<<<(seg_threads + 255) / 256, 256>>>(ids, n);

    final_kernel<<<(out_size + 255) / 256, 256>>>((float*)d_out, out_size);
}

// round 8
// speedup vs baseline: 1.3032x; 1.3032x over previous
#include <cuda_runtime.h>
#include <math.h>

#define N_PIX_MAX 4194304
#define N_BINS    350000
#define TAPS      901
#define HALF      450
#define CONV_THREADS 256
#define RPT       8                         // float2 output-pairs per thread
#define RING      16                        // u64 ring slots (elements mod 16)
#define HTILE     (CONV_THREADS * RPT)      // 2048 (per half)
#define TILE_OUT  (2 * HTILE)               // 4096 outputs per block
#define RAW2      (HTILE + 2*HALF + 64)     // 3012 float2 window (+refill slack)
#define PAD2      (RAW2 + (RAW2 >> 3))      // bank-conflict padding (1 per 8)
#define WSH_N     928                       // taps padded past 901 (zeros) + prefetch slack
#define P2(i)     ((i) + ((i) >> 3))

typedef unsigned long long u64;

// ---------------- device scratch (no allocations allowed) ----------------
__device__ float g_rot[TAPS];
__device__ float g_gauss[TAPS];
__device__ int   g_lo16[2];
__device__ int   g_nt16[2];
__device__ __align__(16) float g_mid[N_PIX_MAX];    // after rotational conv
__device__ __align__(16) float g_conv[N_PIX_MAX];   // after gaussian conv
__device__ float g_sums[N_BINS];
__device__ float g_cnts[N_BINS];

// ---------------- zero the bin accumulators (graph replays!) -------------
__global__ void zero_kernel() {
    int i = blockIdx.x * blockDim.x + threadIdx.x;
    int stride = gridDim.x * blockDim.x;
    for (int j = i; j < N_BINS; j += stride) {
        g_sums[j] = 0.0f;
        g_cnts[j] = 0.0f;
    }
}

// ---------------- build both kernels + support bounds on device ----------
__global__ void setup_kernel(const float* __restrict__ ln_sigma,
                             const float* __restrict__ ln_vsini) {
    __shared__ float red[1024];
    __shared__ int s_lo0, s_hi0, s_lo1, s_hi1;
    int tid = threadIdx.x;
    if (tid == 0) { s_lo0 = TAPS; s_hi0 = -1; s_lo1 = TAPS; s_hi1 = -1; }
    __syncthreads();

    float vsini = 0.9f + expf(ln_vsini[0]);
    float sigma = 0.01f + expf(ln_sigma[0]);

    float w  = 0.0f;   // rotational tap (pre-normalization)
    float gw = 0.0f;   // gaussian tap
    if (tid < TAPS) {
        float g = -4.5f + 0.01f * (float)tid;   // linspace(-4.5,4.5,901)
        float x  = (299792.458f * g / 10500.0f) / vsini;
        float x2 = fminf(x * x, 1.0f);
        if (x2 < 0.99999999f) {
            w = 2.0f * sqrtf(1.0f - x2);
            atomicMin(&s_lo0, tid);
            atomicMax(&s_hi0, tid);
        }
        float e = expf(-0.5f * g * g / (sigma * sigma));
        if (e >= 1e-12f) {                       // relative-to-peak cutoff
            atomicMin(&s_lo1, tid);
            atomicMax(&s_hi1, tid);
        }
        gw = (0.01f / (sigma * sqrtf(2.0f * 3.1415926654f))) * e;
    }

    // block sum of rotational kernel for normalization
    red[tid] = w;
    __syncthreads();
    for (int s = 512; s > 0; s >>= 1) {
        if (tid < s) red[tid] += red[tid + s];
        __syncthreads();
    }
    float total = red[0];

    if (tid < TAPS) {
        g_rot[tid]   = w / total;
        g_gauss[tid] = gw;
    }
    if (tid == 0) {
        // align support to multiples of 16 so the 16-slot ring is static
        int lo0 = s_lo0 & ~15;
        int lo1 = s_lo1 & ~15;
        g_lo16[0] = lo0;  g_nt16[0] = ((s_hi0 - lo0 + 1) + 15) & ~15;
        g_lo16[1] = lo1;  g_nt16[1] = ((s_hi1 - lo1 + 1) + 15) & ~15;
    }
}

// ---------------- tiled conv, packed f32x2, 16-slot ring / 8 accs --------
// Each block produces TILE_OUT=4096 outputs: thread handles 8 pairs
// (o, o+2048). Shared input interleaved float2(in[g], in[g+2048]).
// Ring of 16 elements, 8 consumers per tap: element refilled at tap tau is
// first consumed at tap tau+9 (~100 issues later) -> LDS latency is
// structurally hidden regardless of occupancy.
__global__ void __launch_bounds__(CONV_THREADS)
conv_kernel(const float* __restrict__ ext_in, int n, int which) {
    __shared__ float2 sh2[PAD2];
    __shared__ float  wsh[WSH_N];

    const float* __restrict__ in  = which ? (const float*)g_mid : ext_in;
    float* __restrict__       out = which ? g_conv : g_mid;
    const float* __restrict__ w   = which ? g_gauss : g_rot;
    const int lo16 = g_lo16[which];    // multiple of 16
    const int nt16 = g_nt16[which];    // multiple of 16

    const int tile0 = blockIdx.x * TILE_OUT;
    const int tid   = threadIdx.x;

    for (int j = tid; j < WSH_N; j += CONV_THREADS)
        wsh[j] = (j < TAPS) ? w[j] : 0.0f;
    for (int j = tid; j < RAW2; j += CONV_THREADS) {
        int g1 = tile0 - HALF + j;
        int g2 = g1 + HTILE;
        float a = (g1 >= 0 && g1 < n) ? in[g1] : 0.0f;
        float b = (g2 >= 0 && g2 < n) ? in[g2] : 0.0f;
        sh2[P2(j)] = make_float2(a, b);
    }
    __syncthreads();

    const int base = tid * RPT;        // float2-index of first output pair
    u64 x[RING];                       // slot s holds element (e-base-lo16)%16==s
    u64 acc[RPT];
#pragma unroll
    for (int s = 0; s < RING; ++s)
        x[s] = *(const u64*)&sh2[P2(base + lo16 + s)];
#pragma unroll
    for (int r = 0; r < RPT; ++r)
        acc[r] = 0ull;                 // (0.0f, 0.0f)

    int t = lo16;
    float wv_cur = wsh[t];             // prefetched scalar weight
    for (int it = 0; it < nt16; it += 16, t += 16) {
#pragma unroll
        for (int u = 0; u < 16; ++u) { // tap tau = t + u, phase u
            float wv_nxt = wsh[t + u + 1];           // prefetch next tap's weight
            u64 wp;                                   // pack {w,w} in-register
            asm("mov.b64 %0, {%1, %1};" : "=l"(wp) : "f"(wv_cur));
            // r=0 is the last consumer of slot u (element base+tau)
            asm("fma.rn.f32x2 %0, %1, %2, %0;"
                : "+l"(acc[0]) : "l"(x[u]), "l"(wp));
            // refill slot u with element base+tau+16; first read at tap tau+9
            u64 xfill = *(const u64*)&sh2[P2(base + t + u + 16)];
#pragma unroll
            for (int r = 1; r < RPT; ++r) {
                asm("fma.rn.f32x2 %0, %1, %2, %0;"
                    : "+l"(acc[r]) : "l"(x[(u + r) & 15]), "l"(wp));
            }
            x[u] = xfill;
            wv_cur = wv_nxt;
        }
    }

    // unpack: low 32 bits = first-half output, high = second-half
    float lo_v[RPT], hi_v[RPT];
#pragma unroll
    for (int r = 0; r < RPT; ++r) {
        lo_v[r] = __int_as_float((int)(acc[r] & 0xFFFFFFFFull));
        hi_v[r] = __int_as_float((int)(acc[r] >> 32));
    }

    int o1 = tile0 + base;
    int o2 = o1 + HTILE;
    if (o1 + RPT <= n) {
        *(float4*)(out + o1)     = make_float4(lo_v[0], lo_v[1], lo_v[2], lo_v[3]);
        *(float4*)(out + o1 + 4) = make_float4(lo_v[4], lo_v[5], lo_v[6], lo_v[7]);
    } else {
#pragma unroll
        for (int r = 0; r < RPT; ++r)
            if (o1 + r < n) out[o1 + r] = lo_v[r];
    }
    if (o2 + RPT <= n) {
        *(float4*)(out + o2)     = make_float4(hi_v[0], hi_v[1], hi_v[2], hi_v[3]);
        *(float4*)(out + o2 + 4) = make_float4(hi_v[4], hi_v[5], hi_v[6], hi_v[7]);
    } else {
#pragma unroll
        for (int r = 0; r < RPT; ++r)
            if (o2 + r < n) out[o2 + r] = hi_v[r];
    }
}

// ---------------- sorted segment sum/count (run-length + atomics) --------
__global__ void seg_kernel(const int* __restrict__ ids, int n) {
    long long tidg = (long long)(blockIdx.x * blockDim.x + threadIdx.x);
    int base = (int)(tidg * 8);
    if (base >= n) return;
    int end = base + 8;
    if (end > n) end = n;

    int   cur = ids[base];
    float s = 0.0f, c = 0.0f;
    for (int k = base; k < end; ++k) {
        int id = ids[k];
        if (id != cur) {
            atomicAdd(&g_sums[cur], s);
            atomicAdd(&g_cnts[cur], c);
            cur = id; s = 0.0f; c = 0.0f;
        }
        s += g_conv[k];
        c += 1.0f;
    }
    atomicAdd(&g_sums[cur], s);
    atomicAdd(&g_cnts[cur], c);
}

// ---------------- means, clip, drop first/last bin -----------------------
__global__ void final_kernel(float* __restrict__ out, int n_out) {
    int i = blockIdx.x * blockDim.x + threadIdx.x;
    if (i < n_out) {
        int id = i + 1;
        float c = g_cnts[id];
        float m = g_sums[id] / fmaxf(c, 1.0f);
        out[i] = fminf(fmaxf(m, 0.0f), 1.0f);
    }
}

extern "C" void kernel_launch(void* const* d_in, const int* in_sizes, int n_in,
                              void* d_out, int out_size) {
    const float* flux     = (const float*)d_in[0];
    const float* ln_sigma = (const float*)d_in[1];
    const float* ln_vsini = (const float*)d_in[2];
    const int*   ids      = (const int*)d_in[3];
    int n = in_sizes[0];

    zero_kernel<<<684, 512>>>();
    setup_kernel<<<1, 1024>>>(ln_sigma, ln_vsini);

    int conv_blocks = (n + TILE_OUT - 1) / TILE_OUT;
    conv_kernel<<<conv_blocks, CONV_THREADS>>>(flux, n, 0);
    conv_kernel<<<conv_blocks, CONV_THREADS>>>(flux, n, 1);

    int seg_threads = (n + 7) / 8;
    seg_kernel<<<(seg_threads + 255) / 256, 256>>>(ids, n);

    final_kernel<<<(out_size + 255) / 256, 256>>>((float*)d_out, out_size);
}

// round 9
// speedup vs baseline: 1.4976x; 1.1492x over previous
#include <cuda_runtime.h>
#include <math.h>

#define N_PIX_MAX 4194304
#define N_BINS    350000
#define TAPS      901
#define HALF      450
#define CONV_THREADS 256
#define RPT       8                         // float2 output-pairs per thread
#define RING      8                         // u64 ring slots (elements mod 8)
#define HTILE     (CONV_THREADS * RPT)      // 2048 (per half)
#define TILE_OUT  (2 * HTILE)               // 4096 outputs per block
#define RAW2      (HTILE + 2*HALF + 8)      // 2956 float2 window (+refill slack)
#define PAD2      (RAW2 + (RAW2 >> 3))      // bank-conflict padding (1 per 8)
#define WSH_N     916                       // taps padded past 901 (zeros) + prefetch slack
#define P2(i)     ((i) + ((i) >> 3))

typedef unsigned long long u64;

// ---------------- device scratch (no allocations allowed) ----------------
__device__ float g_rot[TAPS];
__device__ float g_gauss[TAPS];
__device__ int   g_lo8[2];
__device__ int   g_nblk[2];
__device__ __align__(16) float g_mid[N_PIX_MAX];    // after rotational conv
__device__ __align__(16) float g_conv[N_PIX_MAX];   // after gaussian conv
__device__ float g_sums[N_BINS];
__device__ float g_cnts[N_BINS];

// ---------------- zero the bin accumulators (graph replays!) -------------
__global__ void zero_kernel() {
    int i = blockIdx.x * blockDim.x + threadIdx.x;
    int stride = gridDim.x * blockDim.x;
    for (int j = i; j < N_BINS; j += stride) {
        g_sums[j] = 0.0f;
        g_cnts[j] = 0.0f;
    }
}

// ---------------- build both kernels + support bounds on device ----------
__global__ void setup_kernel(const float* __restrict__ ln_sigma,
                             const float* __restrict__ ln_vsini) {
    __shared__ float red[1024];
    __shared__ int s_lo0, s_hi0, s_lo1, s_hi1;
    int tid = threadIdx.x;
    if (tid == 0) { s_lo0 = TAPS; s_hi0 = -1; s_lo1 = TAPS; s_hi1 = -1; }
    __syncthreads();

    float vsini = 0.9f + expf(ln_vsini[0]);
    float sigma = 0.01f + expf(ln_sigma[0]);

    float w  = 0.0f;   // rotational tap (pre-normalization)
    float gw = 0.0f;   // gaussian tap
    if (tid < TAPS) {
        float g = -4.5f + 0.01f * (float)tid;   // linspace(-4.5,4.5,901)
        float x  = (299792.458f * g / 10500.0f) / vsini;
        float x2 = fminf(x * x, 1.0f);
        if (x2 < 0.99999999f) {
            w = 2.0f * sqrtf(1.0f - x2);
            atomicMin(&s_lo0, tid);
            atomicMax(&s_hi0, tid);
        }
        float e = expf(-0.5f * g * g / (sigma * sigma));
        if (e >= 1e-12f) {                       // relative-to-peak cutoff
            atomicMin(&s_lo1, tid);
            atomicMax(&s_hi1, tid);
        }
        gw = (0.01f / (sigma * sqrtf(2.0f * 3.1415926654f))) * e;
    }

    // block sum of rotational kernel for normalization
    red[tid] = w;
    __syncthreads();
    for (int s = 512; s > 0; s >>= 1) {
        if (tid < s) red[tid] += red[tid + s];
        __syncthreads();
    }
    float total = red[0];

    if (tid < TAPS) {
        g_rot[tid]   = w / total;
        g_gauss[tid] = gw;
    }
    if (tid == 0) {
        // align support to multiples of 8 so the conv register ring is static
        int lo0 = s_lo0 & ~7;
        int lo1 = s_lo1 & ~7;
        g_lo8[0]  = lo0;
        g_nblk[0] = (((s_hi0 - lo0 + 1) + 7) & ~7) >> 3;   // 8-tap blocks
        g_lo8[1]  = lo1;
        g_nblk[1] = (((s_hi1 - lo1 + 1) + 7) & ~7) >> 3;
    }
}

// ---------------- tiled conv, packed f32x2, 8-slot ring / 8 accs ---------
// Incremental smem indexing: base+lo8 is a multiple of 8, so within an
// 8-tap block P2(k0+u) = P2(k0)+u (compile-time immediates); across blocks
// the padded index advances by exactly 9. One 32-bit index register each
// for data refill and weights -> minimal ALU + registers.
__global__ void __launch_bounds__(CONV_THREADS, 5)
conv_kernel(const float* __restrict__ ext_in, int n, int which) {
    __shared__ float2 sh2[PAD2];
    __shared__ float  wsh[WSH_N];

    const float* __restrict__ in  = which ? (const float*)g_mid : ext_in;
    float* __restrict__       out = which ? g_conv : g_mid;
    const float* __restrict__ w   = which ? g_gauss : g_rot;
    const int lo8  = g_lo8[which];     // multiple of 8
    const int nblk = g_nblk[which];    // number of 8-tap blocks

    const int tile0 = blockIdx.x * TILE_OUT;
    const int tid   = threadIdx.x;

    for (int j = tid; j < WSH_N; j += CONV_THREADS)
        wsh[j] = (j < TAPS) ? w[j] : 0.0f;
    for (int j = tid; j < RAW2; j += CONV_THREADS) {
        int g1 = tile0 - HALF + j;
        int g2 = g1 + HTILE;
        float a = (g1 >= 0 && g1 < n) ? in[g1] : 0.0f;
        float b = (g2 >= 0 && g2 < n) ? in[g2] : 0.0f;
        sh2[P2(j)] = make_float2(a, b);
    }
    __syncthreads();

    const int base = tid * RPT;        // float2-index of first output pair
    u64 x[RING], acc[RPT];
    int roff = P2(base + lo8);         // padded index of ring start
#pragma unroll
    for (int s = 0; s < RING; ++s) {
        x[s]   = *(const u64*)&sh2[roff + s];     // P2(k0+s)=P2(k0)+s, s<8
        acc[s] = 0ull;                 // (0.0f, 0.0f)
    }
    roff += 9;                         // refill base: P2(k0+8) = P2(k0)+9

    int woff = lo8;                    // weight index (no padding)
    float wv_cur = wsh[woff];          // prefetched scalar weight
    for (int b = 0; b < nblk; ++b) {
#pragma unroll
        for (int u = 0; u < 8; ++u) {  // tap = lo8 + 8*b + u
            float wv_nxt = wsh[woff + u + 1];        // prefetch next tap
            u64 wp;                                   // pack {w,w} in-register
            asm("mov.b64 %0, {%1, %1};" : "=l"(wp) : "f"(wv_cur));
            // r=0 is the last consumer of slot u -> FMA first, then refill
            asm("fma.rn.f32x2 %0, %1, %2, %0;"
                : "+l"(acc[0]) : "l"(x[u]), "l"(wp));
            u64 xfill = *(const u64*)&sh2[roff + u]; // element tap+8
#pragma unroll
            for (int r = 1; r < RPT; ++r) {
                asm("fma.rn.f32x2 %0, %1, %2, %0;"
                    : "+l"(acc[r]) : "l"(x[(u + r) & 7]), "l"(wp));
            }
            x[u] = xfill;
            wv_cur = wv_nxt;
        }
        roff += 9;                     // next block's refill base
        woff += 8;
    }

    // unpack: low 32 bits = first-half output, high = second-half
    float lo_v[RPT], hi_v[RPT];
#pragma unroll
    for (int r = 0; r < RPT; ++r) {
        lo_v[r] = __int_as_float((int)(acc[r] & 0xFFFFFFFFull));
        hi_v[r] = __int_as_float((int)(acc[r] >> 32));
    }

    int o1 = tile0 + base;
    int o2 = o1 + HTILE;
    if (o1 + RPT <= n) {
        *(float4*)(out + o1)     = make_float4(lo_v[0], lo_v[1], lo_v[2], lo_v[3]);
        *(float4*)(out + o1 + 4) = make_float4(lo_v[4], lo_v[5], lo_v[6], lo_v[7]);
    } else {
#pragma unroll
        for (int r = 0; r < RPT; ++r)
            if (o1 + r < n) out[o1 + r] = lo_v[r];
    }
    if (o2 + RPT <= n) {
        *(float4*)(out + o2)     = make_float4(hi_v[0], hi_v[1], hi_v[2], hi_v[3]);
        *(float4*)(out + o2 + 4) = make_float4(hi_v[4], hi_v[5], hi_v[6], hi_v[7]);
    } else {
#pragma unroll
        for (int r = 0; r < RPT; ++r)
            if (o2 + r < n) out[o2 + r] = hi_v[r];
    }
}

// ---------------- sorted segment sum/count (run-length + atomics) --------
__global__ void seg_kernel(const int* __restrict__ ids, int n) {
    long long tidg = (long long)(blockIdx.x * blockDim.x + threadIdx.x);
    int base = (int)(tidg * 8);
    if (base >= n) return;
    int end = base + 8;
    if (end > n) end = n;

    int   cur = ids[base];
    float s = 0.0f, c = 0.0f;
    for (int k = base; k < end; ++k) {
        int id = ids[k];
        if (id != cur) {
            atomicAdd(&g_sums[cur], s);
            atomicAdd(&g_cnts[cur], c);
            cur = id; s = 0.0f; c = 0.0f;
        }
        s += g_conv[k];
        c += 1.0f;
    }
    atomicAdd(&g_sums[cur], s);
    atomicAdd(&g_cnts[cur], c);
}

// ---------------- means, clip, drop first/last bin -----------------------
__global__ void final_kernel(float* __restrict__ out, int n_out) {
    int i = blockIdx.x * blockDim.x + threadIdx.x;
    if (i < n_out) {
        int id = i + 1;
        float c = g_cnts[id];
        float m = g_sums[id] / fmaxf(c, 1.0f);
        out[i] = fminf(fmaxf(m, 0.0f), 1.0f);
    }
}

extern "C" void kernel_launch(void* const* d_in, const int* in_sizes, int n_in,
                              void* d_out, int out_size) {
    const float* flux     = (const float*)d_in[0];
    const float* ln_sigma = (const float*)d_in[1];
    const float* ln_vsini = (const float*)d_in[2];
    const int*   ids      = (const int*)d_in[3];
    int n = in_sizes[0];

    zero_kernel<<<684, 512>>>();
    setup_kernel<<<1, 1024>>>(ln_sigma, ln_vsini);

    int conv_blocks = (n + TILE_OUT - 1) / TILE_OUT;
    conv_kernel<<<conv_blocks, CONV_THREADS>>>(flux, n, 0);
    conv_kernel<<<conv_blocks, CONV_THREADS>>>(flux, n, 1);

    int seg_threads = (n + 7) / 8;
    seg_kernel<<<(seg_threads + 255) / 256, 256>>>(ids, n);

    final_kernel<<<(out_size + 255) / 256, 256>>>((float*)d_out, out_size);
}

// round 10
// speedup vs baseline: 1.6080x; 1.0737x over previous
#include <cuda_runtime.h>
#include <math.h>

#define N_PIX_MAX 4194304
#define N_BINS    350000
#define TAPS      901
#define HALF      450
#define CONV_THREADS 256
#define RPT       8                         // float2 output-pairs per thread
#define RING      8                         // u64 ring slots (elements mod 8)
#define HTILE     (CONV_THREADS * RPT)      // 2048 (per half)
#define TILE_OUT  (2 * HTILE)               // 4096 outputs per block
#define RAW2      (HTILE + 2*HALF + 8)      // 2956 float2 window (+refill slack)
#define PAD2      (RAW2 + (RAW2 >> 3))      // bank-conflict padding (1 per 8)
#define WSH_N     916                       // taps padded past 901 (zeros) + prefetch slack
#define P2(i)     ((i) + ((i) >> 3))

typedef unsigned long long u64;

// ---------------- device scratch (no allocations allowed) ----------------
__device__ float g_rot[TAPS];
__device__ float g_gauss[TAPS];
__device__ int   g_lo8[2];
__device__ int   g_nblk[2];
__device__ __align__(16) float g_mid[N_PIX_MAX];    // after rotational conv
__device__ __align__(16) float g_conv[N_PIX_MAX];   // after gaussian conv
__device__ float g_sums[N_BINS];
__device__ float g_cnts[N_BINS];

// ---------------- zero the bin accumulators (graph replays!) -------------
__global__ void zero_kernel() {
    int i = blockIdx.x * blockDim.x + threadIdx.x;
    int stride = gridDim.x * blockDim.x;
    for (int j = i; j < N_BINS; j += stride) {
        g_sums[j] = 0.0f;
        g_cnts[j] = 0.0f;
    }
}

// ---------------- build both kernels + support bounds on device ----------
__global__ void setup_kernel(const float* __restrict__ ln_sigma,
                             const float* __restrict__ ln_vsini) {
    __shared__ float red[1024];
    __shared__ int s_lo0, s_hi0, s_lo1, s_hi1;
    int tid = threadIdx.x;
    if (tid == 0) { s_lo0 = TAPS; s_hi0 = -1; s_lo1 = TAPS; s_hi1 = -1; }
    __syncthreads();

    float vsini = 0.9f + expf(ln_vsini[0]);
    float sigma = 0.01f + expf(ln_sigma[0]);

    float w  = 0.0f;   // rotational tap (pre-normalization)
    float gw = 0.0f;   // gaussian tap
    if (tid < TAPS) {
        float g = -4.5f + 0.01f * (float)tid;   // linspace(-4.5,4.5,901)
        float x  = (299792.458f * g / 10500.0f) / vsini;
        float x2 = fminf(x * x, 1.0f);
        if (x2 < 0.99999999f) {
            w = 2.0f * sqrtf(1.0f - x2);
            atomicMin(&s_lo0, tid);
            atomicMax(&s_hi0, tid);
        }
        float e = expf(-0.5f * g * g / (sigma * sigma));
        // ~4.5-sigma cutoff: truncated tail mass ~3.4e-6 relative (<< 1e-3 tol)
        if (e >= 4e-5f) {
            atomicMin(&s_lo1, tid);
            atomicMax(&s_hi1, tid);
        }
        gw = (0.01f / (sigma * sqrtf(2.0f * 3.1415926654f))) * e;
    }

    // block sum of rotational kernel for normalization
    red[tid] = w;
    __syncthreads();
    for (int s = 512; s > 0; s >>= 1) {
        if (tid < s) red[tid] += red[tid + s];
        __syncthreads();
    }
    float total = red[0];

    if (tid < TAPS) {
        g_rot[tid]   = w / total;
        g_gauss[tid] = gw;
    }
    if (tid == 0) {
        // align support to multiples of 8 so the conv register ring is static
        int lo0 = s_lo0 & ~7;
        int lo1 = s_lo1 & ~7;
        g_lo8[0]  = lo0;
        g_nblk[0] = (((s_hi0 - lo0 + 1) + 7) & ~7) >> 3;   // 8-tap blocks
        g_lo8[1]  = lo1;
        g_nblk[1] = (((s_hi1 - lo1 + 1) + 7) & ~7) >> 3;
    }
}

// ---------------- tiled conv, packed f32x2, 8-slot ring / 8 accs ---------
// Incremental smem indexing (P2(k0+u)=P2(k0)+u for u<8; +9 per 8-tap block).
// Weights pre-packed {w,w} in smem: one broadcast LDS.64 per tap, no pack
// mov. Weight prefetched one tap ahead; full unroll lets ptxas double-buffer.
__global__ void __launch_bounds__(CONV_THREADS, 5)
conv_kernel(const float* __restrict__ ext_in, int n, int which) {
    __shared__ float2 sh2[PAD2];
    __shared__ float2 wsh2[WSH_N];

    const float* __restrict__ in  = which ? (const float*)g_mid : ext_in;
    float* __restrict__       out = which ? g_conv : g_mid;
    const float* __restrict__ w   = which ? g_gauss : g_rot;
    const int lo8  = g_lo8[which];     // multiple of 8
    const int nblk = g_nblk[which];    // number of 8-tap blocks

    const int tile0 = blockIdx.x * TILE_OUT;
    const int tid   = threadIdx.x;

    for (int j = tid; j < WSH_N; j += CONV_THREADS) {
        float wv = (j < TAPS) ? w[j] : 0.0f;
        wsh2[j] = make_float2(wv, wv);
    }
    for (int j = tid; j < RAW2; j += CONV_THREADS) {
        int g1 = tile0 - HALF + j;
        int g2 = g1 + HTILE;
        float a = (g1 >= 0 && g1 < n) ? in[g1] : 0.0f;
        float b = (g2 >= 0 && g2 < n) ? in[g2] : 0.0f;
        sh2[P2(j)] = make_float2(a, b);
    }
    __syncthreads();

    const int base = tid * RPT;        // float2-index of first output pair
    u64 x[RING], acc[RPT];
    int roff = P2(base + lo8);         // padded index of ring start
#pragma unroll
    for (int s = 0; s < RING; ++s) {
        x[s]   = *(const u64*)&sh2[roff + s];     // P2(k0+s)=P2(k0)+s, s<8
        acc[s] = 0ull;                 // (0.0f, 0.0f)
    }
    roff += 9;                         // refill base: P2(k0+8) = P2(k0)+9

    int woff = lo8;                    // weight index (no padding)
    u64 wp_cur = *(const u64*)&wsh2[woff];       // prefetched packed weight
    for (int b = 0; b < nblk; ++b) {
#pragma unroll
        for (int u = 0; u < 8; ++u) {  // tap = lo8 + 8*b + u
            u64 wp_nxt = *(const u64*)&wsh2[woff + u + 1];  // prefetch next tap
            // r=0 is the last consumer of slot u -> FMA first, then refill
            asm("fma.rn.f32x2 %0, %1, %2, %0;"
                : "+l"(acc[0]) : "l"(x[u]), "l"(wp_cur));
            u64 xfill = *(const u64*)&sh2[roff + u];        // element tap+8
#pragma unroll
            for (int r = 1; r < RPT; ++r) {
                asm("fma.rn.f32x2 %0, %1, %2, %0;"
                    : "+l"(acc[r]) : "l"(x[(u + r) & 7]), "l"(wp_cur));
            }
            x[u] = xfill;
            wp_cur = wp_nxt;
        }
        roff += 9;                     // next block's refill base
        woff += 8;
    }

    // unpack: low 32 bits = first-half output, high = second-half
    float lo_v[RPT], hi_v[RPT];
#pragma unroll
    for (int r = 0; r < RPT; ++r) {
        lo_v[r] = __int_as_float((int)(acc[r] & 0xFFFFFFFFull));
        hi_v[r] = __int_as_float((int)(acc[r] >> 32));
    }

    int o1 = tile0 + base;
    int o2 = o1 + HTILE;
    if (o1 + RPT <= n) {
        *(float4*)(out + o1)     = make_float4(lo_v[0], lo_v[1], lo_v[2], lo_v[3]);
        *(float4*)(out + o1 + 4) = make_float4(lo_v[4], lo_v[5], lo_v[6], lo_v[7]);
    } else {
#pragma unroll
        for (int r = 0; r < RPT; ++r)
            if (o1 + r < n) out[o1 + r] = lo_v[r];
    }
    if (o2 + RPT <= n) {
        *(float4*)(out + o2)     = make_float4(hi_v[0], hi_v[1], hi_v[2], hi_v[3]);
        *(float4*)(out + o2 + 4) = make_float4(hi_v[4], hi_v[5], hi_v[6], hi_v[7]);
    } else {
#pragma unroll
        for (int r = 0; r < RPT; ++r)
            if (o2 + r < n) out[o2 + r] = hi_v[r];
    }
}

// ---------------- sorted segment sum/count (run-length + atomics) --------
__global__ void seg_kernel(const int* __restrict__ ids, int n) {
    long long tidg = (long long)(blockIdx.x * blockDim.x + threadIdx.x);
    int base = (int)(tidg * 8);
    if (base >= n) return;
    int end = base + 8;
    if (end > n) end = n;

    int   cur = ids[base];
    float s = 0.0f, c = 0.0f;
    for (int k = base; k < end; ++k) {
        int id = ids[k];
        if (id != cur) {
            atomicAdd(&g_sums[cur], s);
            atomicAdd(&g_cnts[cur], c);
            cur = id; s = 0.0f; c = 0.0f;
        }
        s += g_conv[k];
        c += 1.0f;
    }
    atomicAdd(&g_sums[cur], s);
    atomicAdd(&g_cnts[cur], c);
}

// ---------------- means, clip, drop first/last bin -----------------------
__global__ void final_kernel(float* __restrict__ out, int n_out) {
    int i = blockIdx.x * blockDim.x + threadIdx.x;
    if (i < n_out) {
        int id = i + 1;
        float c = g_cnts[id];
        float m = g_sums[id] / fmaxf(c, 1.0f);
        out[i] = fminf(fmaxf(m, 0.0f), 1.0f);
    }
}

extern "C" void kernel_launch(void* const* d_in, const int* in_sizes, int n_in,
                              void* d_out, int out_size) {
    const float* flux     = (const float*)d_in[0];
    const float* ln_sigma = (const float*)d_in[1];
    const float* ln_vsini = (const float*)d_in[2];
    const int*   ids      = (const int*)d_in[3];
    int n = in_sizes[0];

    zero_kernel<<<684, 512>>>();
    setup_kernel<<<1, 1024>>>(ln_sigma, ln_vsini);

    int conv_blocks = (n + TILE_OUT - 1) / TILE_OUT;
    conv_kernel<<<conv_blocks, CONV_THREADS>>>(flux, n, 0);
    conv_kernel<<<conv_blocks, CONV_THREADS>>>(flux, n, 1);

    int seg_threads = (n + 7) / 8;
    seg_kernel<<<(seg_threads + 255) / 256, 256>>>(ids, n);

    final_kernel<<<(out_size + 255) / 256, 256>>>((float*)d_out, out_size);
}